// round 8
// baseline (speedup 1.0000x reference)
#include <cuda_runtime.h>
#include <cuda_fp16.h>
#include <math.h>

// Problem constants
#define B_    16
#define CIN   384
#define L0    65536   // B * 64*64
#define L1    16384   // B * 32*32
#define N0_   4096
#define N1_   1024
#define CDIM_ 128
#define KK_   64

// weight buffer layout per scale: w1[1152*384] | w2f[128*512] | w2s[64*512 used]
#define W1SZ  (1152 * CIN)
#define W2FSZ (128 * 512)
#define W2SSZ (128 * 512)
#define WSTRIDE (W1SZ + W2FSZ + W2SSZ)

// -------- scratch (device globals; no allocation allowed) --------
__device__ __half g_xt  [CIN * L0];         // x transposed, fp16 [C, B*N0]
__device__ __half g_x1t [CIN * L1];         // pooled x, fp16 [C, B*N1]
__device__ __half g_hidden[1152 * L0];      // relu(hidden), fp16 (reused per scale)
__device__ __half g_feath[CDIM_ * (L0 + L1)];  // local_feat fp16, s0 | s1
__device__ __half g_Zh  [65 * (L0 + L1)];   // E = exp(scores|dustbin) fp16, s0 | s1
__device__ float  g_out [2 * B_ * CDIM_ * KK_];
__device__ __half g_wbuf[2 * WSTRIDE];      // fp16 weights per scale
__device__ float  g_bbuf[2 * 1152];         // layer-1 biases per scale
__device__ float  g_c   [B_ * (N0_ + N1_)]; // sinkhorn column scaling, s0 | s1

__device__ __forceinline__ const __half* xptr(int id) {
    return id == 0 ? g_xt : (id == 1 ? g_x1t : g_hidden);
}

__device__ __forceinline__ float4 h4_to_f4(uint2 u) {
    __half2 a = *(__half2*)&u.x;
    __half2 b = *(__half2*)&u.y;
    float2 fa = __half22float2(a);
    float2 fb = __half22float2(b);
    return make_float4(fa.x, fa.y, fb.x, fb.y);
}

// -------- merged transpose + pool (x read once, float2-coalesced) --------
__global__ void tpose_pool_k(const float* __restrict__ x) {
    int idx = blockIdx.x * 256 + threadIdx.x;   // total 384*16384
    int c = idx >> 14;
    int l = idx & 16383;
    int b = l >> 10;
    int p = l & 1023;
    int i = p >> 5, j = p & 31;
    const float* xb = x + ((long)(b * CIN + c) << 12);
    int r0 = (2 * i) * 64 + 2 * j;
    float2 t0 = *(const float2*)&xb[r0];
    float2 t1 = *(const float2*)&xb[r0 + 64];
    __half* xt = g_xt + ((long)c << 16) + (b << 12);
    *(__half2*)&xt[r0]      = __floats2half2_rn(t0.x, t0.y);
    *(__half2*)&xt[r0 + 64] = __floats2half2_rn(t1.x, t1.y);
    g_x1t[idx] = __float2half_rn(0.25f * (t0.x + t0.y + t1.x + t1.y));
}

__global__ void zero_k() {
    int i = blockIdx.x * 256 + threadIdx.x;
    if (i < 2 * B_ * CDIM_ * KK_) g_out[i] = 0.f;
}

// prep per-scale: concat+convert w1, convert w2f, convert w2s (64 rows)
__global__ void prep_k(int s,
                       const float* __restrict__ fw1, const float* __restrict__ fb1,
                       const float* __restrict__ sw1, const float* __restrict__ sb1,
                       const float* __restrict__ dw1, const float* __restrict__ db1,
                       const float* __restrict__ fw2, const float* __restrict__ sw2) {
    int idx = blockIdx.x * 256 + threadIdx.x;
    __half* wb = g_wbuf + (long)s * WSTRIDE;
    const int A1 = 512 * CIN, A2 = 1024 * CIN;
    if (idx < W1SZ) {
        float v;
        if (idx < A1) v = fw1[idx];
        else if (idx < A2) v = sw1[idx - A1];
        else v = dw1[idx - A2];
        wb[idx] = __float2half_rn(v);
    }
    if (idx < W2FSZ) wb[W1SZ + idx] = __float2half_rn(fw2[idx]);
    if (idx < 64 * 512) wb[W1SZ + W2FSZ + idx] = __float2half_rn(sw2[idx]);
    if (idx < 1152)
        g_bbuf[s * 1152 + idx] =
            (idx < 512) ? fb1[idx] : (idx < 1024) ? sb1[idx - 512] : db1[idx - 1024];
}

// -------- async / ldmatrix helpers --------
__device__ __forceinline__ void cp16s(unsigned saddr, const void* g) {
    asm volatile("cp.async.cg.shared.global [%0], [%1], 16;\n" :: "r"(saddr), "l"(g));
}
__device__ __forceinline__ void cp_commit() { asm volatile("cp.async.commit_group;\n"); }
__device__ __forceinline__ void cp_wait0()  { asm volatile("cp.async.wait_group 0;\n"); }
__device__ __forceinline__ void cp_wait1()  { asm volatile("cp.async.wait_group 1;\n"); }

__device__ __forceinline__ void ldsm_x4(unsigned* r, unsigned addr) {
    asm volatile("ldmatrix.sync.aligned.m8n8.x4.shared.b16 {%0,%1,%2,%3}, [%4];"
                 : "=r"(r[0]), "=r"(r[1]), "=r"(r[2]), "=r"(r[3]) : "r"(addr));
}
__device__ __forceinline__ void ldsm_x2t(unsigned* r, unsigned addr) {
    asm volatile("ldmatrix.sync.aligned.m8n8.x2.trans.shared.b16 {%0,%1}, [%2];"
                 : "=r"(r[0]), "=r"(r[1]) : "r"(addr));
}

// -------- fp16 tensor-core GEMM: C[M,L] = W[M,K] @ X[K,L] (+bias, epilogue) --------
// CTA tile (MW*32) x 128, BK=32, 256 threads = 8 warps, 2 CTAs/SM:
//   MW=4: warps 4m x 2n (warp 32m x 64n);  MW=2: warps 2m x 4n (warp 32m x 32n)
// MODE: 0 = bias -> feat; 1 = relu -> hidden; 2 = exp -> E   (all fp16 stores)
template <int MODE, int MW>
__global__ void __launch_bounds__(256, 2)
hgemm(long woff, const float* __restrict__ biasp, long boff,
      int xid, long xoff, long coff, int K, int L, int Mstore) {
    constexpr int NT = (MW == 4) ? 8 : 4;
    const __half* W = g_wbuf + woff;
    const float* bias = biasp ? biasp : (g_bbuf + boff);
    const __half* X = xptr(xid) + xoff;
    __half* Ch = ((MODE == 0) ? g_feath : (MODE == 1) ? g_hidden : g_Zh) + coff;

    __shared__ __half sA[2][MW * 32 * 40];
    __shared__ __half sB[2][32 * 136];

    int tid = threadIdx.x, lane = tid & 31, warp = tid >> 5;
    int wm = (MW == 4) ? (warp >> 1) : (warp >> 2);
    int wn = (MW == 4) ? (warp & 1) : (warp & 3);
    int g = lane >> 2, tg = lane & 3;
    int bm = blockIdx.x * (MW * 32);
    long bl = (long)blockIdx.y * 128;

    unsigned aB0 = (unsigned)__cvta_generic_to_shared(&sA[0][0]);
    unsigned aB1 = (unsigned)__cvta_generic_to_shared(&sA[1][0]);
    unsigned bB0 = (unsigned)__cvta_generic_to_shared(&sB[0][0]);
    unsigned bB1 = (unsigned)__cvta_generic_to_shared(&sB[1][0]);

    float acc[2][NT][4];
#pragma unroll
    for (int mt = 0; mt < 2; mt++)
#pragma unroll
        for (int n = 0; n < NT; n++)
#pragma unroll
            for (int i = 0; i < 4; i++) acc[mt][n][i] = 0.f;

    int ntiles = K / 32;

#define PREFETCH(kt, buf)                                                        \
    {                                                                            \
        unsigned aS = (buf) ? aB1 : aB0;                                         \
        unsigned bS = (buf) ? bB1 : bB0;                                         \
        _Pragma("unroll")                                                        \
        for (int i = 0; i < MW / 2; i++) {                                       \
            int ch = tid + i * 256;                                              \
            int m = ch >> 2, q = ch & 3;                                         \
            cp16s(aS + (unsigned)(m * 40 + q * 8) * 2u,                          \
                  W + (long)(bm + m) * K + (kt) * 32 + q * 8);                   \
        }                                                                        \
        _Pragma("unroll")                                                        \
        for (int i = 0; i < 2; i++) {                                            \
            int ch = tid + i * 256;                                              \
            int k = ch >> 4, n8 = ch & 15;                                       \
            cp16s(bS + (unsigned)(k * 136 + n8 * 8) * 2u,                        \
                  X + (long)((kt) * 32 + k) * L + bl + n8 * 8);                  \
        }                                                                        \
        cp_commit();                                                             \
    }

    PREFETCH(0, 0);

    for (int kt = 0; kt < ntiles; kt++) {
        int buf = kt & 1;
        if (kt + 1 < ntiles) {
            PREFETCH(kt + 1, buf ^ 1);
            cp_wait1();
        } else {
            cp_wait0();
        }
        __syncthreads();

        unsigned aS = buf ? aB1 : aB0;
        unsigned bS = buf ? bB1 : bB0;
        int rbase = (lane & 7) + ((lane >> 3) & 1) * 8;
        int kof = (lane >> 4) * 8;

#pragma unroll
        for (int ks = 0; ks < 2; ks++) {
            unsigned ra[2][4];
#pragma unroll
            for (int mt = 0; mt < 2; mt++) {
                int row = wm * 32 + mt * 16 + rbase;
                ldsm_x4(ra[mt], aS + (unsigned)(row * 40 + ks * 16 + kof) * 2u);
            }
            unsigned rb[NT][2];
            int kk = ks * 16 + (lane & 15);
#pragma unroll
            for (int n = 0; n < NT; n++) {
                int n0 = wn * (NT * 8) + n * 8;
                ldsm_x2t(rb[n], bS + (unsigned)(kk * 136 + n0) * 2u);
            }
#pragma unroll
            for (int mt = 0; mt < 2; mt++)
#pragma unroll
                for (int n = 0; n < NT; n++) {
                    asm volatile(
                        "mma.sync.aligned.m16n8k16.row.col.f32.f16.f16.f32 "
                        "{%0,%1,%2,%3}, {%4,%5,%6,%7}, {%8,%9}, {%0,%1,%2,%3};\n"
                        : "+f"(acc[mt][n][0]), "+f"(acc[mt][n][1]),
                          "+f"(acc[mt][n][2]), "+f"(acc[mt][n][3])
                        : "r"(ra[mt][0]), "r"(ra[mt][1]), "r"(ra[mt][2]), "r"(ra[mt][3]),
                          "r"(rb[n][0]), "r"(rb[n][1]));
                }
        }
        __syncthreads();
    }
#undef PREFETCH

    // epilogue (fp16 stores for all modes)
#pragma unroll
    for (int mt = 0; mt < 2; mt++) {
        int r0 = bm + wm * 32 + mt * 16 + g;
        int r1 = r0 + 8;
        float bv0 = (r0 < Mstore) ? bias[r0] : 0.f;
        float bv1 = (r1 < Mstore) ? bias[r1] : 0.f;
#pragma unroll
        for (int n = 0; n < NT; n++) {
            long cc = bl + wn * (NT * 8) + n * 8 + tg * 2;
            if (r0 < Mstore) {
                float vx = acc[mt][n][0] + bv0;
                float vy = acc[mt][n][1] + bv0;
                if (MODE == 1) { vx = fmaxf(vx, 0.f); vy = fmaxf(vy, 0.f); }
                if (MODE == 2) { vx = __expf(vx); vy = __expf(vy); }
                *(__half2*)&Ch[(long)r0 * L + cc] = __floats2half2_rn(vx, vy);
            }
            if (r1 < Mstore) {
                float vx = acc[mt][n][2] + bv1;
                float vy = acc[mt][n][3] + bv1;
                if (MODE == 1) { vx = fmaxf(vx, 0.f); vy = fmaxf(vy, 0.f); }
                if (MODE == 2) { vx = __expf(vx); vy = __expf(vy); }
                *(__half2*)&Ch[(long)r1 * L + cc] = __floats2half2_rn(vx, vy);
            }
        }
    }
}

// -------- dustbin: E[64, l] = exp(db2 + dw2 . hidden_d[:, l]), half2 --------
__global__ void dustbin_k(const float* __restrict__ dw2, const float* __restrict__ db2,
                          int L, long zoff) {
    __shared__ float w[128];
    int tid = threadIdx.x;
    if (tid < 128) w[tid] = dw2[tid];
    __syncthreads();
    long l = ((long)blockIdx.x * 256 + tid) * 2;
    const __half* h = g_hidden + (long)1024 * L + l;
    float a0 = db2[0], a1 = a0;
#pragma unroll 8
    for (int k = 0; k < 128; k++) {
        float2 hv = __half22float2(*(const __half2*)&h[(long)k * L]);
        a0 += w[k] * hv.x;
        a1 += w[k] * hv.y;
    }
    *(__half2*)&g_Zh[zoff + (long)64 * L + l] = __floats2half2_rn(__expf(a0), __expf(a1));
}

// -------- Sinkhorn both scales (32 blocks), exp space, fp16 E --------
__global__ void __launch_bounds__(1024) sinkhorn2_k() {
    int blk = blockIdx.x;
    int s = blk >> 4, b = blk & 15;
    int N = s ? N1_ : N0_;
    int L = s ? L1 : L0;
    long zb = (s ? (long)65 * L0 : 0L) + (long)b * N;
    long cb = (s ? (long)B_ * N0_ : 0L) + (long)b * N;

    __shared__ float4 c4[1024];
    __shared__ float r[72];
    int tid = threadIdx.x, lane = tid & 31, warp = tid >> 5;
    float mu = 1.0f / 65.0f;
    float nu = 1.0f / (float)N;
    int n4 = N / 4;
    int l4 = L / 4;

    for (int i = tid; i < n4; i += 1024) c4[i] = make_float4(1.f, 1.f, 1.f, 1.f);
    __syncthreads();

    for (int it = 0; it < 3; it++) {
        for (int k = warp; k < 65; k += 32) {
            const uint2* er = (const uint2*)(g_Zh + (long)k * L + zb);
            float sm = 0.f;
            for (int i = lane; i < n4; i += 32) {
                float4 e = h4_to_f4(er[i]);
                float4 cc = c4[i];
                sm += e.x * cc.x + e.y * cc.y + e.z * cc.z + e.w * cc.w;
            }
#pragma unroll
            for (int off = 16; off; off >>= 1) sm += __shfl_xor_sync(0xffffffffu, sm, off);
            if (lane == 0) r[k] = mu / sm;
        }
        __syncthreads();
        for (int i = tid; i < n4; i += 1024) {
            const uint2* base = (const uint2*)(g_Zh + zb) + i;
            float4 a = make_float4(0.f, 0.f, 0.f, 0.f);
#pragma unroll 5
            for (int k = 0; k < 65; k++) {
                float4 e = h4_to_f4(base[(long)k * l4]);
                float rk = r[k];
                a.x += e.x * rk; a.y += e.y * rk; a.z += e.z * rk; a.w += e.w * rk;
            }
            c4[i] = make_float4(nu / a.x, nu / a.y, nu / a.z, nu / a.w);
        }
        __syncthreads();
    }
    float4* co = (float4*)(g_c + cb);
    for (int i = tid; i < n4; i += 1024) co[i] = c4[i];
}

// -------- einsum: out[b,c,k] += sum_n feat[c,n] * E[k,n] * c_n --------
__global__ void __launch_bounds__(256)
einsum_k(int obase, int N, int L, long foff, long zoff, long cboff) {
    int b = blockIdx.x;
    int nc0 = blockIdx.y * 128;
    __shared__ float Fs[32][132];
    __shared__ float Ps[32][68];
    int tid = threadIdx.x, tx = tid & 15, ty = tid >> 4;
    long base = (long)b * N;

    float acc[8][4];
#pragma unroll
    for (int i = 0; i < 8; i++)
#pragma unroll
        for (int j = 0; j < 4; j++) acc[i][j] = 0.f;

    for (int nc = nc0; nc < nc0 + 128; nc += 32) {
#pragma unroll
        for (int i = 0; i < 16; i++) {
            int e = tid + i * 256;
            int cch = e >> 5, n = e & 31;
            Fs[n][cch] = __half2float(g_feath[foff + (long)cch * L + base + nc + n]);
        }
        {
            int n = tid & 31;
            float cv = g_c[cboff + base + nc + n];
#pragma unroll
            for (int i = 0; i < 8; i++) {
                int e = tid + i * 256;
                int k = e >> 5;
                Ps[n][k] = __half2float(g_Zh[zoff + (long)k * L + base + nc + n]) * cv;
            }
        }
        __syncthreads();
#pragma unroll
        for (int kk = 0; kk < 32; kk++) {
            float a[8], bb[4];
            float4 t;
            t = *(const float4*)&Fs[kk][ty * 4];      a[0]=t.x; a[1]=t.y; a[2]=t.z; a[3]=t.w;
            t = *(const float4*)&Fs[kk][ty * 4 + 64]; a[4]=t.x; a[5]=t.y; a[6]=t.z; a[7]=t.w;
            t = *(const float4*)&Ps[kk][tx * 4];      bb[0]=t.x; bb[1]=t.y; bb[2]=t.z; bb[3]=t.w;
#pragma unroll
            for (int i = 0; i < 8; i++)
#pragma unroll
                for (int j = 0; j < 4; j++) acc[i][j] += a[i] * bb[j];
        }
        __syncthreads();
    }

    float* outp = g_out + ((long)(obase + b)) * (CDIM_ * KK_);
#pragma unroll
    for (int i = 0; i < 8; i++) {
        int rr = (i < 4) ? (ty * 4 + i) : (64 + ty * 4 + i - 4);
#pragma unroll
        for (int j = 0; j < 4; j++)
            atomicAdd(&outp[rr * 64 + tx * 4 + j], acc[i][j]);
    }
}

// -------- final normalization --------
__global__ void __launch_bounds__(256) final_k(float* __restrict__ out) {
    int b = blockIdx.x, tid = threadIdx.x;
    __shared__ float d[8192];
    __shared__ float cn[2][64];
    __shared__ float red[9];
    if (tid < 128) cn[tid >> 6][tid & 63] = 0.f;
    __syncthreads();
    const float* o0 = g_out + (long)b * 8192;
    const float* o1 = g_out + (long)(B_ + b) * 8192;
    for (int e = tid; e < 8192; e += 256) {
        float v0 = o0[e], v1 = o1[e];
        atomicAdd(&cn[0][e & 63], v0 * v0);
        atomicAdd(&cn[1][e & 63], v1 * v1);
    }
    __syncthreads();
    if (tid < 128) {
        float nn = sqrtf(cn[tid >> 6][tid & 63]);
        cn[tid >> 6][tid & 63] = 1.f / fmaxf(nn, 1e-12f);
    }
    __syncthreads();
    float ss = 0.f;
    for (int e = tid; e < 8192; e += 256) {
        int k = e & 63;
        float dv = 0.5f * (o0[e] * cn[0][k] + o1[e] * cn[1][k]);
        d[e] = dv;
        ss += dv * dv;
    }
#pragma unroll
    for (int off = 16; off; off >>= 1) ss += __shfl_xor_sync(0xffffffffu, ss, off);
    if ((tid & 31) == 0) red[tid >> 5] = ss;
    __syncthreads();
    if (tid == 0) {
        float t = 0.f;
        for (int i = 0; i < 8; i++) t += red[i];
        red[8] = 1.f / fmaxf(sqrtf(t), 1e-12f);
    }
    __syncthreads();
    float inv = red[8];
    for (int e = tid; e < 8192; e += 256) out[(long)b * 8192 + e] = d[e] * inv;
}

extern "C" void kernel_launch(void* const* d_in, const int* in_sizes, int n_in,
                              void* d_out, int out_size) {
    (void)in_sizes; (void)n_in; (void)out_size;
    const float* x = (const float*)d_in[0];

    for (int s = 0; s < 2; s++) {
        int base = 1 + s * 12;
        prep_k<<<1728, 256>>>(s,
            (const float*)d_in[base + 0], (const float*)d_in[base + 1],
            (const float*)d_in[base + 4], (const float*)d_in[base + 5],
            (const float*)d_in[base + 8], (const float*)d_in[base + 9],
            (const float*)d_in[base + 2], (const float*)d_in[base + 6]);
    }
    tpose_pool_k<<<(CIN * L1) / 256, 256>>>(x);
    zero_k<<<64, 256>>>();

    for (int s = 0; s < 2; s++) {
        int base = 1 + s * 12;
        const float* fb2 = (const float*)d_in[base + 3];
        const float* sb2 = (const float*)d_in[base + 7];
        const float* dw2 = (const float*)d_in[base + 10];
        const float* db2 = (const float*)d_in[base + 11];

        int L = s ? L1 : L0;
        int xid = s ? 1 : 0;
        long ws = (long)s * WSTRIDE;
        long foff = s ? (long)CDIM_ * L0 : 0L;
        long zoff = s ? (long)65 * L0 : 0L;

        // fused layer-1 (relu + fp16 store): M=1152
        hgemm<1, 4><<<dim3(9, L / 128), 256>>>(ws, nullptr, (long)s * 1152,
                                               xid, 0L, 0L, CIN, L, 1152);
        // layer-2 feat (bias + fp16 store): M=128
        hgemm<0, 4><<<dim3(1, L / 128), 256>>>(ws + W1SZ, fb2, 0L,
                                               2, 0L, foff, 512, L, 128);
        // layer-2 score (exp + fp16 store -> E): true M=64 tiles
        hgemm<2, 2><<<dim3(1, L / 128), 256>>>(ws + W1SZ + W2FSZ, sb2, 0L,
                                               2, (long)512 * L, zoff, 512, L, 64);
        dustbin_k<<<L / 512, 256>>>(dw2, db2, L, zoff);
    }

    // both scales' Sinkhorn concurrently (32 blocks)
    sinkhorn2_k<<<32, 1024>>>();

    einsum_k<<<dim3(B_, N0_ / 128), 256>>>(0, N0_, L0, 0L, 0L, 0L);
    einsum_k<<<dim3(B_, N1_ / 128), 256>>>(B_, N1_, L1,
                                           (long)CDIM_ * L0, (long)65 * L0,
                                           (long)B_ * N0_);

    final_k<<<B_, 256>>>((float*)d_out);
}

// round 9
// speedup vs baseline: 1.0943x; 1.0943x over previous
#include <cuda_runtime.h>
#include <cuda_fp16.h>
#include <math.h>

// Problem constants
#define B_    16
#define CIN   384
#define L0    65536   // B * 64*64
#define L1    16384   // B * 32*32
#define N0_   4096
#define N1_   1024
#define CDIM_ 128
#define KK_   64

// weight buffer layout per scale: w1[1152*384] | w2f[128*512] | w2s[64*512 used]
#define W1SZ  (1152 * CIN)
#define W2FSZ (128 * 512)
#define W2SSZ (128 * 512)
#define WSTRIDE (W1SZ + W2FSZ + W2SSZ)

// -------- scratch (device globals; no allocation allowed) --------
__device__ __half g_xt  [CIN * L0];         // x transposed, fp16 [C, B*N0]
__device__ __half g_x1t [CIN * L1];         // pooled x, fp16 [C, B*N1]
__device__ __half g_hidden[1152 * L0];      // relu(hidden), fp16 (reused per scale)
__device__ __half g_feath[CDIM_ * (L0 + L1)];  // local_feat fp16, s0 | s1
__device__ __half g_Zh  [65 * (L0 + L1)];   // E = exp(scores|dustbin) fp16, s0 | s1
__device__ float  g_out [2 * B_ * CDIM_ * KK_];
__device__ __half g_wbuf[2 * WSTRIDE];      // fp16 weights per scale
__device__ float  g_bbuf[2 * 1152];         // layer-1 biases per scale
__device__ float  g_c   [B_ * (N0_ + N1_)]; // sinkhorn column scaling, s0 | s1

__device__ __forceinline__ const __half* xptr(int id) {
    return id == 0 ? g_xt : (id == 1 ? g_x1t : g_hidden);
}

__device__ __forceinline__ float4 h4_to_f4(uint2 u) {
    __half2 a = *(__half2*)&u.x;
    __half2 b = *(__half2*)&u.y;
    float2 fa = __half22float2(a);
    float2 fb = __half22float2(b);
    return make_float4(fa.x, fa.y, fb.x, fb.y);
}

// -------- merged transpose + pool (x read once, float2-coalesced) --------
__global__ void tpose_pool_k(const float* __restrict__ x) {
    int idx = blockIdx.x * 256 + threadIdx.x;   // total 384*16384
    int c = idx >> 14;
    int l = idx & 16383;
    int b = l >> 10;
    int p = l & 1023;
    int i = p >> 5, j = p & 31;
    const float* xb = x + ((long)(b * CIN + c) << 12);
    int r0 = (2 * i) * 64 + 2 * j;
    float2 t0 = *(const float2*)&xb[r0];
    float2 t1 = *(const float2*)&xb[r0 + 64];
    __half* xt = g_xt + ((long)c << 16) + (b << 12);
    *(__half2*)&xt[r0]      = __floats2half2_rn(t0.x, t0.y);
    *(__half2*)&xt[r0 + 64] = __floats2half2_rn(t1.x, t1.y);
    g_x1t[idx] = __float2half_rn(0.25f * (t0.x + t0.y + t1.x + t1.y));
}

// prep both scales (grid.y = s); also zeroes g_out
__global__ void prep_k(const float* __restrict__ fw1_0, const float* __restrict__ fb1_0,
                       const float* __restrict__ sw1_0, const float* __restrict__ sb1_0,
                       const float* __restrict__ dw1_0, const float* __restrict__ db1_0,
                       const float* __restrict__ fw2_0, const float* __restrict__ sw2_0,
                       const float* __restrict__ fw1_1, const float* __restrict__ fb1_1,
                       const float* __restrict__ sw1_1, const float* __restrict__ sb1_1,
                       const float* __restrict__ dw1_1, const float* __restrict__ db1_1,
                       const float* __restrict__ fw2_1, const float* __restrict__ sw2_1) {
    int idx = blockIdx.x * 256 + threadIdx.x;
    int s = blockIdx.y;
    const float* fw1 = s ? fw1_1 : fw1_0;
    const float* fb1 = s ? fb1_1 : fb1_0;
    const float* sw1 = s ? sw1_1 : sw1_0;
    const float* sb1 = s ? sb1_1 : sb1_0;
    const float* dw1 = s ? dw1_1 : dw1_0;
    const float* db1 = s ? db1_1 : db1_0;
    const float* fw2 = s ? fw2_1 : fw2_0;
    const float* sw2 = s ? sw2_1 : sw2_0;

    __half* wb = g_wbuf + (long)s * WSTRIDE;
    const int A1 = 512 * CIN, A2 = 1024 * CIN;
    if (idx < W1SZ) {
        float v;
        if (idx < A1) v = fw1[idx];
        else if (idx < A2) v = sw1[idx - A1];
        else v = dw1[idx - A2];
        wb[idx] = __float2half_rn(v);
    }
    if (idx < W2FSZ) wb[W1SZ + idx] = __float2half_rn(fw2[idx]);
    if (idx < 64 * 512) wb[W1SZ + W2FSZ + idx] = __float2half_rn(sw2[idx]);
    if (idx < 1152)
        g_bbuf[s * 1152 + idx] =
            (idx < 512) ? fb1[idx] : (idx < 1024) ? sb1[idx - 512] : db1[idx - 1024];
    if (s == 0 && idx < 2 * B_ * CDIM_ * KK_) g_out[idx] = 0.f;
}

// -------- async / ldmatrix helpers --------
__device__ __forceinline__ void cp16s(unsigned saddr, const void* g) {
    asm volatile("cp.async.cg.shared.global [%0], [%1], 16;\n" :: "r"(saddr), "l"(g));
}
__device__ __forceinline__ void cp_commit() { asm volatile("cp.async.commit_group;\n"); }
__device__ __forceinline__ void cp_wait0()  { asm volatile("cp.async.wait_group 0;\n"); }
__device__ __forceinline__ void cp_wait1()  { asm volatile("cp.async.wait_group 1;\n"); }

__device__ __forceinline__ void ldsm_x4(unsigned* r, unsigned addr) {
    asm volatile("ldmatrix.sync.aligned.m8n8.x4.shared.b16 {%0,%1,%2,%3}, [%4];"
                 : "=r"(r[0]), "=r"(r[1]), "=r"(r[2]), "=r"(r[3]) : "r"(addr));
}
__device__ __forceinline__ void ldsm_x2t(unsigned* r, unsigned addr) {
    asm volatile("ldmatrix.sync.aligned.m8n8.x2.trans.shared.b16 {%0,%1}, [%2];"
                 : "=r"(r[0]), "=r"(r[1]) : "r"(addr));
}
__device__ __forceinline__ void hmma16816(float* d, const unsigned* a, const unsigned* b) {
    asm volatile(
        "mma.sync.aligned.m16n8k16.row.col.f32.f16.f16.f32 "
        "{%0,%1,%2,%3}, {%4,%5,%6,%7}, {%8,%9}, {%0,%1,%2,%3};\n"
        : "+f"(d[0]), "+f"(d[1]), "+f"(d[2]), "+f"(d[3])
        : "r"(a[0]), "r"(a[1]), "r"(a[2]), "r"(a[3]), "r"(b[0]), "r"(b[1]));
}

// -------- fp16 tensor-core GEMM: C[M,L] = W[M,K] @ X[K,L] (+bias, epilogue) --------
// CTA tile (MW*32) x 128, BK=32, 256 threads = 8 warps:
//   MW=4: warps 4m x 2n (warp 32m x 64n);  MW=2: warps 2m x 4n (warp 32m x 32n)
// MODE: 0 = bias -> feat; 1 = relu -> hidden; 2 = exp -> E   (all fp16 stores)
template <int MODE, int MW>
__global__ void __launch_bounds__(256)
hgemm(long woff, const float* __restrict__ biasp, long boff,
      int xid, long xoff, long coff, int K, int L, int Mstore) {
    constexpr int NT = (MW == 4) ? 8 : 4;
    const __half* W = g_wbuf + woff;
    const float* bias = biasp ? biasp : (g_bbuf + boff);
    const __half* X = xptr(xid) + xoff;
    __half* Ch = ((MODE == 0) ? g_feath : (MODE == 1) ? g_hidden : g_Zh) + coff;

    __shared__ __half sA[2][MW * 32 * 40];
    __shared__ __half sB[2][32 * 136];

    int tid = threadIdx.x, lane = tid & 31, warp = tid >> 5;
    int wm = (MW == 4) ? (warp >> 1) : (warp >> 2);
    int wn = (MW == 4) ? (warp & 1) : (warp & 3);
    int g = lane >> 2, tg = lane & 3;
    int bm = blockIdx.x * (MW * 32);
    long bl = (long)blockIdx.y * 128;

    unsigned aB0 = (unsigned)__cvta_generic_to_shared(&sA[0][0]);
    unsigned aB1 = (unsigned)__cvta_generic_to_shared(&sA[1][0]);
    unsigned bB0 = (unsigned)__cvta_generic_to_shared(&sB[0][0]);
    unsigned bB1 = (unsigned)__cvta_generic_to_shared(&sB[1][0]);

    float acc[2][NT][4];
#pragma unroll
    for (int mt = 0; mt < 2; mt++)
#pragma unroll
        for (int n = 0; n < NT; n++)
#pragma unroll
            for (int i = 0; i < 4; i++) acc[mt][n][i] = 0.f;

    int ntiles = K / 32;

#define PREFETCH(kt, buf)                                                        \
    {                                                                            \
        unsigned aS = (buf) ? aB1 : aB0;                                         \
        unsigned bS = (buf) ? bB1 : bB0;                                         \
        _Pragma("unroll")                                                        \
        for (int i = 0; i < MW / 2; i++) {                                       \
            int ch = tid + i * 256;                                              \
            int m = ch >> 2, q = ch & 3;                                         \
            cp16s(aS + (unsigned)(m * 40 + q * 8) * 2u,                          \
                  W + (long)(bm + m) * K + (kt) * 32 + q * 8);                   \
        }                                                                        \
        _Pragma("unroll")                                                        \
        for (int i = 0; i < 2; i++) {                                            \
            int ch = tid + i * 256;                                              \
            int k = ch >> 4, n8 = ch & 15;                                       \
            cp16s(bS + (unsigned)(k * 136 + n8 * 8) * 2u,                        \
                  X + (long)((kt) * 32 + k) * L + bl + n8 * 8);                  \
        }                                                                        \
        cp_commit();                                                             \
    }

    PREFETCH(0, 0);

    for (int kt = 0; kt < ntiles; kt++) {
        int buf = kt & 1;
        if (kt + 1 < ntiles) {
            PREFETCH(kt + 1, buf ^ 1);
            cp_wait1();
        } else {
            cp_wait0();
        }
        __syncthreads();

        unsigned aS = buf ? aB1 : aB0;
        unsigned bS = buf ? bB1 : bB0;
        int rbase = (lane & 7) + ((lane >> 3) & 1) * 8;
        int kof = (lane >> 4) * 8;

#pragma unroll
        for (int ks = 0; ks < 2; ks++) {
            unsigned ra[2][4];
#pragma unroll
            for (int mt = 0; mt < 2; mt++) {
                int row = wm * 32 + mt * 16 + rbase;
                ldsm_x4(ra[mt], aS + (unsigned)(row * 40 + ks * 16 + kof) * 2u);
            }
            unsigned rb[NT][2];
            int kk = ks * 16 + (lane & 15);
#pragma unroll
            for (int n = 0; n < NT; n++) {
                int n0 = wn * (NT * 8) + n * 8;
                ldsm_x2t(rb[n], bS + (unsigned)(kk * 136 + n0) * 2u);
            }
#pragma unroll
            for (int mt = 0; mt < 2; mt++)
#pragma unroll
                for (int n = 0; n < NT; n++)
                    hmma16816(acc[mt][n], ra[mt], rb[n]);
        }
        __syncthreads();
    }
#undef PREFETCH

    // epilogue (fp16 stores for all modes)
#pragma unroll
    for (int mt = 0; mt < 2; mt++) {
        int r0 = bm + wm * 32 + mt * 16 + g;
        int r1 = r0 + 8;
        float bv0 = (r0 < Mstore) ? bias[r0] : 0.f;
        float bv1 = (r1 < Mstore) ? bias[r1] : 0.f;
#pragma unroll
        for (int n = 0; n < NT; n++) {
            long cc = bl + wn * (NT * 8) + n * 8 + tg * 2;
            if (r0 < Mstore) {
                float vx = acc[mt][n][0] + bv0;
                float vy = acc[mt][n][1] + bv0;
                if (MODE == 1) { vx = fmaxf(vx, 0.f); vy = fmaxf(vy, 0.f); }
                if (MODE == 2) { vx = __expf(vx); vy = __expf(vy); }
                *(__half2*)&Ch[(long)r0 * L + cc] = __floats2half2_rn(vx, vy);
            }
            if (r1 < Mstore) {
                float vx = acc[mt][n][2] + bv1;
                float vy = acc[mt][n][3] + bv1;
                if (MODE == 1) { vx = fmaxf(vx, 0.f); vy = fmaxf(vy, 0.f); }
                if (MODE == 2) { vx = __expf(vx); vy = __expf(vy); }
                *(__half2*)&Ch[(long)r1 * L + cc] = __floats2half2_rn(vx, vy);
            }
        }
    }
}

// -------- dustbin: E[64, l] = exp(db2 + dw2 . hidden_d[:, l]), half2 --------
__global__ void dustbin_k(const float* __restrict__ dw2, const float* __restrict__ db2,
                          int L, long zoff) {
    __shared__ float w[128];
    int tid = threadIdx.x;
    if (tid < 128) w[tid] = dw2[tid];
    __syncthreads();
    long l = ((long)blockIdx.x * 256 + tid) * 2;
    const __half* h = g_hidden + (long)1024 * L + l;
    float a0 = db2[0], a1 = a0;
#pragma unroll 8
    for (int k = 0; k < 128; k++) {
        float2 hv = __half22float2(*(const __half2*)&h[(long)k * L]);
        a0 += w[k] * hv.x;
        a1 += w[k] * hv.y;
    }
    *(__half2*)&g_Zh[zoff + (long)64 * L + l] = __floats2half2_rn(__expf(a0), __expf(a1));
}

// -------- Sinkhorn both scales (32 blocks), exp space, fp16 E --------
__global__ void __launch_bounds__(1024) sinkhorn2_k() {
    int blk = blockIdx.x;
    int s = blk >> 4, b = blk & 15;
    int N = s ? N1_ : N0_;
    int L = s ? L1 : L0;
    long zb = (s ? (long)65 * L0 : 0L) + (long)b * N;
    long cb = (s ? (long)B_ * N0_ : 0L) + (long)b * N;

    __shared__ float4 c4[1024];
    __shared__ float r[72];
    int tid = threadIdx.x, lane = tid & 31, warp = tid >> 5;
    float mu = 1.0f / 65.0f;
    float nu = 1.0f / (float)N;
    int n4 = N / 4;
    int l4 = L / 4;

    for (int i = tid; i < n4; i += 1024) c4[i] = make_float4(1.f, 1.f, 1.f, 1.f);
    __syncthreads();

    for (int it = 0; it < 3; it++) {
        for (int k = warp; k < 65; k += 32) {
            const uint2* er = (const uint2*)(g_Zh + (long)k * L + zb);
            float sm = 0.f;
            for (int i = lane; i < n4; i += 32) {
                float4 e = h4_to_f4(er[i]);
                float4 cc = c4[i];
                sm += e.x * cc.x + e.y * cc.y + e.z * cc.z + e.w * cc.w;
            }
#pragma unroll
            for (int off = 16; off; off >>= 1) sm += __shfl_xor_sync(0xffffffffu, sm, off);
            if (lane == 0) r[k] = mu / sm;
        }
        __syncthreads();
        for (int i = tid; i < n4; i += 1024) {
            const uint2* base = (const uint2*)(g_Zh + zb) + i;
            float4 a = make_float4(0.f, 0.f, 0.f, 0.f);
#pragma unroll 5
            for (int k = 0; k < 65; k++) {
                float4 e = h4_to_f4(base[(long)k * l4]);
                float rk = r[k];
                a.x += e.x * rk; a.y += e.y * rk; a.z += e.z * rk; a.w += e.w * rk;
            }
            c4[i] = make_float4(nu / a.x, nu / a.y, nu / a.z, nu / a.w);
        }
        __syncthreads();
    }
    float4* co = (float4*)(g_c + cb);
    for (int i = tid; i < n4; i += 1024) co[i] = c4[i];
}

// -------- tensor-core einsum: outT[k,c] += sum_n P[k,n] * feat[c,n] --------
// A = P (M=64 rows k, K=n) row-major; B = feat [c][n] row-major = col-major [n, c].
// 8 warps: 4m x 2n; warp tile m16 x c64. Chunk of NCH tokens per block.
__global__ void __launch_bounds__(256)
einsum_mma(int obase, int N, int L, long foff, long zoff, long cboff, int NCH) {
    int b = blockIdx.x;
    int nc0 = blockIdx.y * NCH;
    __shared__ __half sP[64 * 40];
    __shared__ __half sF[128 * 40];

    int tid = threadIdx.x, lane = tid & 31, warp = tid >> 5;
    int wm = warp >> 1, wn = warp & 1;
    int m0 = wm * 16, c0 = wn * 64;
    long base = (long)b * N;

    unsigned sPa = (unsigned)__cvta_generic_to_shared(&sP[0]);
    unsigned sFa = (unsigned)__cvta_generic_to_shared(&sF[0]);

    float acc[8][4];
#pragma unroll
    for (int n = 0; n < 8; n++)
#pragma unroll
        for (int i = 0; i < 4; i++) acc[n][i] = 0.f;

    for (int nt = 0; nt < NCH; nt += 32) {
        long nbase = base + nc0 + nt;
        // feat tile: 128 c-rows x 32 tokens via cp.async (16B each, 2/thread)
#pragma unroll
        for (int i = 0; i < 2; i++) {
            int ch = tid + i * 256;
            int c = ch >> 2, q = ch & 3;
            cp16s(sFa + (unsigned)(c * 40 + q * 8) * 2u,
                  g_feath + foff + (long)c * L + nbase + q * 8);
        }
        cp_commit();
        // P tile: 64 k-rows x 32 tokens, P = E * c_n (fp16)
#pragma unroll
        for (int i = 0; i < 4; i++) {
            int ch = tid + i * 256;
            int k = ch >> 4, j = (ch & 15) * 2;
            float2 e = __half22float2(*(const __half2*)&g_Zh[zoff + (long)k * L + nbase + j]);
            float2 cv = *(const float2*)&g_c[cboff + nbase + j];
            *(__half2*)&sP[k * 40 + j] = __floats2half2_rn(e.x * cv.x, e.y * cv.y);
        }
        cp_wait0();
        __syncthreads();

        int rbase = (lane & 7) + ((lane >> 3) & 1) * 8;
        int kof = (lane >> 4) * 8;
        int grp = lane >> 3, rr = lane & 7;
#pragma unroll
        for (int ks = 0; ks < 2; ks++) {
            unsigned ra[4];
            ldsm_x4(ra, sPa + (unsigned)((m0 + rbase) * 40 + ks * 16 + kof) * 2u);
#pragma unroll
            for (int ci = 0; ci < 4; ci++) {
                unsigned rb[4];
                int row = c0 + ci * 16 + (grp >> 1) * 8 + rr;
                ldsm_x4(rb, sFa + (unsigned)(row * 40 + ks * 16 + (grp & 1) * 8) * 2u);
                hmma16816(acc[ci * 2 + 0], ra, rb);
                hmma16816(acc[ci * 2 + 1], ra, rb + 2);
            }
        }
        __syncthreads();
    }

    // scatter: C[m=k_out][n=c]; out layout [c*64 + k]
    float* outp = g_out + (long)(obase + b) * (CDIM_ * KK_);
    int g = lane >> 2, tg = lane & 3;
#pragma unroll
    for (int nf = 0; nf < 8; nf++) {
        int cact = c0 + nf * 8 + tg * 2;
        int k0 = m0 + g;
        atomicAdd(&outp[cact * 64 + k0],           acc[nf][0]);
        atomicAdd(&outp[(cact + 1) * 64 + k0],     acc[nf][1]);
        atomicAdd(&outp[cact * 64 + k0 + 8],       acc[nf][2]);
        atomicAdd(&outp[(cact + 1) * 64 + k0 + 8], acc[nf][3]);
    }
}

// -------- final normalization --------
__global__ void __launch_bounds__(256) final_k(float* __restrict__ out) {
    int b = blockIdx.x, tid = threadIdx.x;
    __shared__ float d[8192];
    __shared__ float cn[2][64];
    __shared__ float red[9];
    if (tid < 128) cn[tid >> 6][tid & 63] = 0.f;
    __syncthreads();
    const float* o0 = g_out + (long)b * 8192;
    const float* o1 = g_out + (long)(B_ + b) * 8192;
    for (int e = tid; e < 8192; e += 256) {
        float v0 = o0[e], v1 = o1[e];
        atomicAdd(&cn[0][e & 63], v0 * v0);
        atomicAdd(&cn[1][e & 63], v1 * v1);
    }
    __syncthreads();
    if (tid < 128) {
        float nn = sqrtf(cn[tid >> 6][tid & 63]);
        cn[tid >> 6][tid & 63] = 1.f / fmaxf(nn, 1e-12f);
    }
    __syncthreads();
    float ss = 0.f;
    for (int e = tid; e < 8192; e += 256) {
        int k = e & 63;
        float dv = 0.5f * (o0[e] * cn[0][k] + o1[e] * cn[1][k]);
        d[e] = dv;
        ss += dv * dv;
    }
#pragma unroll
    for (int off = 16; off; off >>= 1) ss += __shfl_xor_sync(0xffffffffu, ss, off);
    if ((tid & 31) == 0) red[tid >> 5] = ss;
    __syncthreads();
    if (tid == 0) {
        float t = 0.f;
        for (int i = 0; i < 8; i++) t += red[i];
        red[8] = 1.f / fmaxf(sqrtf(t), 1e-12f);
    }
    __syncthreads();
    float inv = red[8];
    for (int e = tid; e < 8192; e += 256) out[(long)b * 8192 + e] = d[e] * inv;
}

extern "C" void kernel_launch(void* const* d_in, const int* in_sizes, int n_in,
                              void* d_out, int out_size) {
    (void)in_sizes; (void)n_in; (void)out_size;
    const float* x = (const float*)d_in[0];

    prep_k<<<dim3(1728, 2), 256>>>(
        (const float*)d_in[1],  (const float*)d_in[2],
        (const float*)d_in[5],  (const float*)d_in[6],
        (const float*)d_in[9],  (const float*)d_in[10],
        (const float*)d_in[3],  (const float*)d_in[7],
        (const float*)d_in[13], (const float*)d_in[14],
        (const float*)d_in[17], (const float*)d_in[18],
        (const float*)d_in[21], (const float*)d_in[22],
        (const float*)d_in[15], (const float*)d_in[19]);
    tpose_pool_k<<<(CIN * L1) / 256, 256>>>(x);

    for (int s = 0; s < 2; s++) {
        int base = 1 + s * 12;
        const float* fb2 = (const float*)d_in[base + 3];
        const float* sb2 = (const float*)d_in[base + 7];
        const float* dw2 = (const float*)d_in[base + 10];
        const float* db2 = (const float*)d_in[base + 11];

        int L = s ? L1 : L0;
        int xid = s ? 1 : 0;
        long ws = (long)s * WSTRIDE;
        long foff = s ? (long)CDIM_ * L0 : 0L;
        long zoff = s ? (long)65 * L0 : 0L;

        // fused layer-1 (relu + fp16 store): M=1152
        hgemm<1, 4><<<dim3(9, L / 128), 256>>>(ws, nullptr, (long)s * 1152,
                                               xid, 0L, 0L, CIN, L, 1152);
        // layer-2 feat (bias + fp16 store): M=128
        hgemm<0, 4><<<dim3(1, L / 128), 256>>>(ws + W1SZ, fb2, 0L,
                                               2, 0L, foff, 512, L, 128);
        // layer-2 score (exp + fp16 store -> E): true M=64 tiles
        hgemm<2, 2><<<dim3(1, L / 128), 256>>>(ws + W1SZ + W2FSZ, sb2, 0L,
                                               2, (long)512 * L, zoff, 512, L, 64);
        dustbin_k<<<L / 512, 256>>>(dw2, db2, L, zoff);
    }

    // both scales' Sinkhorn concurrently (32 blocks)
    sinkhorn2_k<<<32, 1024>>>();

    // tensor-core einsum, split over token chunks
    einsum_mma<<<dim3(B_, 8), 256>>>(0, N0_, L0, 0L, 0L, 0L, 512);
    einsum_mma<<<dim3(B_, 2), 256>>>(B_, N1_, L1,
                                     (long)CDIM_ * L0, (long)65 * L0,
                                     (long)B_ * N0_, 512);

    final_k<<<B_, 256>>>((float*)d_out);
}